// round 14
// baseline (speedup 1.0000x reference)
#include <cuda_runtime.h>
#include <cuda_fp16.h>
#include <math.h>
#include <float.h>

#define N 4096
#define IN_F 256
#define H0 64
#define H1 64
#define H2 32
#define CAP 256
#define SLOPE 0.01f
#define WH_BLOCKS 192

// -------- scratch (device globals; no allocation) --------
__device__ unsigned short g_mask[3 * N * 256];   // 16 nonzero bits per thread-chunk
__device__ int    g_nbr_idx[N * CAP];            // only the selected relation
__device__ int    g_nbr_cnt[N];
__device__ __half g_WhH[3 * N * H0];             // fp16 Wh (gather traffic halved)
__device__ float  g_ssrc[3 * N];
__device__ float  g_sdst[3 * N];
__device__ float  g_hr[3 * N * H0];
__device__ float  g_support[N * H1];
__device__ float  g_support2[N * H2];
__device__ float  g_resid[N * H2];
__device__ float2 g_WgC[H1 * H2];                // {Wg1[k][j], Wr[j][k]} combined

__device__ __forceinline__ float leaky(float v) { return v >= 0.f ? v : SLOPE * v; }

__device__ __forceinline__ int read_relation(const void* p) {
    int r = *reinterpret_cast<const int*>(p);
    if (r < 0 || r > 2) {
        float fv = *reinterpret_cast<const float*>(p);
        r = (int)fv;
        if (r < 0 || r > 2) r = 0;
    }
    return r;
}

__device__ __forceinline__ unsigned mask16(float4 v0, float4 v1, float4 v2, float4 v3) {
    unsigned mask = 0;
    if (v0.x > 0.f) mask |= 1u << 0;  if (v0.y > 0.f) mask |= 1u << 1;
    if (v0.z > 0.f) mask |= 1u << 2;  if (v0.w > 0.f) mask |= 1u << 3;
    if (v1.x > 0.f) mask |= 1u << 4;  if (v1.y > 0.f) mask |= 1u << 5;
    if (v1.z > 0.f) mask |= 1u << 6;  if (v1.w > 0.f) mask |= 1u << 7;
    if (v2.x > 0.f) mask |= 1u << 8;  if (v2.y > 0.f) mask |= 1u << 9;
    if (v2.z > 0.f) mask |= 1u << 10; if (v2.w > 0.f) mask |= 1u << 11;
    if (v3.x > 0.f) mask |= 1u << 12; if (v3.y > 0.f) mask |= 1u << 13;
    if (v3.z > 0.f) mask |= 1u << 14; if (v3.w > 0.f) mask |= 1u << 15;
    return mask;
}

// ============ kernel A: wh tiles + pure streaming adjacency scan ==========
__device__ void wh_body(int b,
                        const float* __restrict__ x,
                        const float* __restrict__ W1, const float* __restrict__ a1,
                        const float* __restrict__ W2, const float* __restrict__ a2,
                        const float* __restrict__ W3, const float* __restrict__ a3) {
    int r = b >> 6;
    int row0 = (b & 63) * 64;
    const float* W = (r == 0) ? W1 : (r == 1) ? W2 : W3;
    const float* a = (r == 0) ? a1 : (r == 1) ? a2 : a3;
    int tid = threadIdx.x;
    int rg = tid >> 4;
    int cgp = tid & 15;

    __shared__ float sx[64][64];
    __shared__ float sW[64][64];

    float4 acc[4];
#pragma unroll
    for (int q = 0; q < 4; q++) acc[q] = make_float4(0.f, 0.f, 0.f, 0.f);

    for (int k0 = 0; k0 < IN_F; k0 += 64) {
        __syncthreads();
#pragma unroll
        for (int q = 0; q < 4; q++) {
            int lin = tid + q * 256;
            int rr = lin >> 4, c4 = (lin & 15) << 2;
            *(float4*)&sx[rr][c4] = *(const float4*)(x + (size_t)(row0 + rr) * IN_F + k0 + c4);
        }
#pragma unroll
        for (int q = 0; q < 4; q++) {
            int lin = tid + q * 256;
            int kr = lin >> 4, c4 = (lin & 15) << 2;
            *(float4*)&sW[kr][c4] = *(const float4*)(W + (size_t)(k0 + kr) * H0 + c4);
        }
        __syncthreads();
#pragma unroll 16
        for (int kk = 0; kk < 64; kk++) {
            float4 wv = *(float4*)&sW[kk][cgp * 4];
            float xv0 = sx[rg * 4 + 0][kk];
            float xv1 = sx[rg * 4 + 1][kk];
            float xv2 = sx[rg * 4 + 2][kk];
            float xv3 = sx[rg * 4 + 3][kk];
            acc[0].x = fmaf(xv0, wv.x, acc[0].x); acc[0].y = fmaf(xv0, wv.y, acc[0].y);
            acc[0].z = fmaf(xv0, wv.z, acc[0].z); acc[0].w = fmaf(xv0, wv.w, acc[0].w);
            acc[1].x = fmaf(xv1, wv.x, acc[1].x); acc[1].y = fmaf(xv1, wv.y, acc[1].y);
            acc[1].z = fmaf(xv1, wv.z, acc[1].z); acc[1].w = fmaf(xv1, wv.w, acc[1].w);
            acc[2].x = fmaf(xv2, wv.x, acc[2].x); acc[2].y = fmaf(xv2, wv.y, acc[2].y);
            acc[2].z = fmaf(xv2, wv.z, acc[2].z); acc[2].w = fmaf(xv2, wv.w, acc[2].w);
            acc[3].x = fmaf(xv3, wv.x, acc[3].x); acc[3].y = fmaf(xv3, wv.y, acc[3].y);
            acc[3].z = fmaf(xv3, wv.z, acc[3].z); acc[3].w = fmaf(xv3, wv.w, acc[3].w);
        }
    }

    float4 av = *(const float4*)(a + cgp * 4);
    float4 ad = *(const float4*)(a + H0 + cgp * 4);
#pragma unroll
    for (int ri = 0; ri < 4; ri++) {
        int grow = row0 + rg * 4 + ri;
        __half2 h01 = __float22half2_rn(make_float2(acc[ri].x, acc[ri].y));
        __half2 h23 = __float22half2_rn(make_float2(acc[ri].z, acc[ri].w));
        __half2* dst = (__half2*)(g_WhH + ((size_t)r * N + grow) * H0 + cgp * 4);
        dst[0] = h01;
        dst[1] = h23;
        float ps = acc[ri].x * av.x + acc[ri].y * av.y + acc[ri].z * av.z + acc[ri].w * av.w;
        float pd = acc[ri].x * ad.x + acc[ri].y * ad.y + acc[ri].z * ad.z + acc[ri].w * ad.w;
#pragma unroll
        for (int off = 8; off > 0; off >>= 1) {
            ps += __shfl_down_sync(0xffffffffu, ps, off, 16);
            pd += __shfl_down_sync(0xffffffffu, pd, off, 16);
        }
        if (cgp == 0) { g_ssrc[r * N + grow] = ps; g_sdst[r * N + grow] = pd; }
    }
}

__device__ void scan_body(int b, const float* __restrict__ adj) {
    // 2 rows per block; pure stream: LDG x8, popcount masks, STG. No barriers.
    int r = b >> 11;
    int i0 = (b & 2047) * 2;
    int id0 = r * N + i0;
    int tid = threadIdx.x;
    const float4* rowA = (const float4*)(adj + (size_t)id0 * N);
    const float4* rowB = rowA + (N / 4);
    float4 va0 = rowA[tid], va1 = rowA[tid + 256], va2 = rowA[tid + 512], va3 = rowA[tid + 768];
    float4 vb0 = rowB[tid], vb1 = rowB[tid + 256], vb2 = rowB[tid + 512], vb3 = rowB[tid + 768];
    unsigned m0 = mask16(va0, va1, va2, va3);
    unsigned m1 = mask16(vb0, vb1, vb2, vb3);
    g_mask[(size_t)id0 * 256 + tid]       = (unsigned short)m0;
    g_mask[((size_t)id0 + 1) * 256 + tid] = (unsigned short)m1;
}

__global__ void __launch_bounds__(256)
scanwh_kernel(const float* __restrict__ x, const float* __restrict__ adj,
              const float* __restrict__ W1, const float* __restrict__ a1,
              const float* __restrict__ W2, const float* __restrict__ a2,
              const float* __restrict__ W3, const float* __restrict__ a3) {
    if (blockIdx.x < WH_BLOCKS)
        wh_body(blockIdx.x, x, W1, a1, W2, a2, W3, a3);
    else
        scan_body(blockIdx.x - WH_BLOCKS, adj);
}

// ===== kernel B: attention from masks (compaction+softmax+gather), 2 rows ==
__global__ void __launch_bounds__(256)
attn_kernel(const void* __restrict__ relation) {
    __shared__ int      s_idx[2][CAP];
    __shared__ float    s_w[2][CAP];
    __shared__ unsigned s_wsum[8];
    __shared__ float    s_m[2][8];
    __shared__ float    s_s[2][8];
    __shared__ float    s_acc[2][4][H0];

    int b = blockIdx.x;
    int r = b >> 11;
    int i0 = (b & 2047) * 2;
    int id0 = r * N + i0;
    int tid = threadIdx.x;
    int lane = tid & 31, wid = tid >> 5;

    unsigned m0 = g_mask[(size_t)id0 * 256 + tid];
    unsigned m1 = g_mask[((size_t)id0 + 1) * 256 + tid];
    unsigned pc = (unsigned)__popc(m0) | ((unsigned)__popc(m1) << 16);

    unsigned pre = pc;
#pragma unroll
    for (int off = 1; off < 32; off <<= 1) {
        unsigned nv = __shfl_up_sync(0xffffffffu, pre, off);
        if (lane >= off) pre += nv;
    }
    if (lane == 31) s_wsum[wid] = pre;
    __syncthreads();
    unsigned wbase = 0, totp = 0;
#pragma unroll
    for (int w = 0; w < 8; w++) {
        unsigned v = s_wsum[w];
        if (w < wid) wbase += v;
        totp += v;
    }
    unsigned startp = wbase + pre - pc;
    int pos0 = startp & 0xFFFFu;
    int pos1 = startp >> 16;
    int total0 = totp & 0xFFFFu;
    int total1 = totp >> 16;

    // compaction (both rows)
    {
        unsigned mm = m0;
        int pos = pos0;
        while (mm) {
            int bb = __ffs(mm) - 1;
            mm &= mm - 1;
            int q = bb >> 2, j = bb & 3;
            int col = ((tid + (q << 8)) << 2) + j;
            if (pos < CAP) s_idx[0][pos] = col;
            pos++;
        }
        mm = m1;
        pos = pos1;
        while (mm) {
            int bb = __ffs(mm) - 1;
            mm &= mm - 1;
            int q = bb >> 2, j = bb & 3;
            int col = ((tid + (q << 8)) << 2) + j;
            if (pos < CAP) s_idx[1][pos] = col;
            pos++;
        }
    }
    __syncthreads();
    int cnt0 = min(total0, CAP);
    int cnt1 = min(total1, CAP);

    // persist lists only for the relation the GNN layers use
    int relv = read_relation(relation);
    if (r == relv) {
        int* gl0 = g_nbr_idx + (size_t)i0 * CAP;
        int* gl1 = gl0 + CAP;
        for (int k = tid; k < cnt0; k += 256) gl0[k] = s_idx[0][k];
        for (int k = tid; k < cnt1; k += 256) gl1[k] = s_idx[1][k];
        if (tid == 0) { g_nbr_cnt[i0] = total0; g_nbr_cnt[i0 + 1] = total1; }
    }

    // --- scores (one element per thread per row)
    float si0 = g_ssrc[id0];
    float si1 = g_ssrc[id0 + 1];
    const float* sdstR = g_sdst + r * N;
    float sc0 = (tid < cnt0) ? leaky(si0 + sdstR[s_idx[0][tid]]) : -FLT_MAX;
    float sc1 = (tid < cnt1) ? leaky(si1 + sdstR[s_idx[1][tid]]) : -FLT_MAX;

    float mm0 = sc0, mm1 = sc1;
#pragma unroll
    for (int off = 16; off > 0; off >>= 1) {
        mm0 = fmaxf(mm0, __shfl_xor_sync(0xffffffffu, mm0, off));
        mm1 = fmaxf(mm1, __shfl_xor_sync(0xffffffffu, mm1, off));
    }
    if (lane == 0) { s_m[0][wid] = mm0; s_m[1][wid] = mm1; }
    __syncthreads();
    float bm0 = s_m[0][0], bm1 = s_m[1][0];
#pragma unroll
    for (int w = 1; w < 8; w++) {
        bm0 = fmaxf(bm0, s_m[0][w]);
        bm1 = fmaxf(bm1, s_m[1][w]);
    }

    float e0 = (tid < cnt0) ? __expf(sc0 - bm0) : 0.f;
    float e1 = (tid < cnt1) ? __expf(sc1 - bm1) : 0.f;
    s_w[0][tid] = e0;
    s_w[1][tid] = e1;
    float su0 = e0, su1 = e1;
#pragma unroll
    for (int off = 16; off > 0; off >>= 1) {
        su0 += __shfl_xor_sync(0xffffffffu, su0, off);
        su1 += __shfl_xor_sync(0xffffffffu, su1, off);
    }
    if (lane == 0) { s_s[0][wid] = su0; s_s[1][wid] = su1; }
    __syncthreads();
    float bs0 = s_s[0][0], bs1 = s_s[1][0];
#pragma unroll
    for (int w = 1; w < 8; w++) { bs0 += s_s[0][w]; bs1 += s_s[1][w]; }
    float inv0 = 1.f / bs0;
    float inv1 = 1.f / bs1;

    // --- weighted gathers (fp16 Wh rows)
    int f = tid & 63;
    int kc = tid >> 6;
    const __half* WhR = g_WhH + (size_t)r * N * H0;
    float acc0 = 0.f, acc1 = 0.f;
    int k = kc;
    for (; k + 12 < cnt0; k += 16) {
        int j0 = s_idx[0][k], j1 = s_idx[0][k + 4], j2 = s_idx[0][k + 8], j3 = s_idx[0][k + 12];
        float w0 = s_w[0][k], w1 = s_w[0][k + 4], w2 = s_w[0][k + 8], w3 = s_w[0][k + 12];
        float p0 = __half2float(WhR[(size_t)j0 * H0 + f]);
        float p1 = __half2float(WhR[(size_t)j1 * H0 + f]);
        float p2 = __half2float(WhR[(size_t)j2 * H0 + f]);
        float p3 = __half2float(WhR[(size_t)j3 * H0 + f]);
        acc0 = fmaf(w0, p0, acc0);
        acc0 = fmaf(w1, p1, acc0);
        acc0 = fmaf(w2, p2, acc0);
        acc0 = fmaf(w3, p3, acc0);
    }
    for (; k < cnt0; k += 4)
        acc0 = fmaf(s_w[0][k], __half2float(WhR[(size_t)s_idx[0][k] * H0 + f]), acc0);
    k = kc;
    for (; k + 12 < cnt1; k += 16) {
        int j0 = s_idx[1][k], j1 = s_idx[1][k + 4], j2 = s_idx[1][k + 8], j3 = s_idx[1][k + 12];
        float w0 = s_w[1][k], w1 = s_w[1][k + 4], w2 = s_w[1][k + 8], w3 = s_w[1][k + 12];
        float p0 = __half2float(WhR[(size_t)j0 * H0 + f]);
        float p1 = __half2float(WhR[(size_t)j1 * H0 + f]);
        float p2 = __half2float(WhR[(size_t)j2 * H0 + f]);
        float p3 = __half2float(WhR[(size_t)j3 * H0 + f]);
        acc1 = fmaf(w0, p0, acc1);
        acc1 = fmaf(w1, p1, acc1);
        acc1 = fmaf(w2, p2, acc1);
        acc1 = fmaf(w3, p3, acc1);
    }
    for (; k < cnt1; k += 4)
        acc1 = fmaf(s_w[1][k], __half2float(WhR[(size_t)s_idx[1][k] * H0 + f]), acc1);
    s_acc[0][kc][f] = acc0;
    s_acc[1][kc][f] = acc1;
    __syncthreads();
    if (tid < 128) {
        int rr = tid >> 6, f2 = tid & 63;
        float inv = rr ? inv1 : inv0;
        float o = (s_acc[rr][0][f2] + s_acc[rr][1][f2] + s_acc[rr][2][f2] + s_acc[rr][3][f2]) * inv;
        g_hr[(size_t)(id0 + rr) * H0 + f2] = o;
    }
}

// ================= kernel 3: fuse + support + combined-weight prep ========
__global__ void __launch_bounds__(256)
fuse_kernel(const float* __restrict__ Wg0, const float* __restrict__ Wg1,
            const float* __restrict__ Wr) {
    int tid = threadIdx.x;
    int rr = tid >> 6;
    int f = tid & 63;
    int i = blockIdx.x * 4 + rr;
    if (blockIdx.x == 0) {
#pragma unroll
        for (int t = tid; t < H1 * H2; t += 256) {
            int k = t >> 5, j = t & 31;
            g_WgC[t] = make_float2(Wg1[k * H2 + j], Wr[j * H1 + k]);
        }
    }
    __shared__ float hp[4][H0];
    float v = (g_hr[(size_t)i * H0 + f] +
               g_hr[((size_t)N + i) * H0 + f] +
               g_hr[((size_t)2 * N + i) * H0 + f]) * (1.f / 3.f);
    hp[rr][f] = 1.f / (1.f + __expf(-v));
    __syncthreads();
    float acc = 0.f;
#pragma unroll 16
    for (int k = 0; k < H0; k++) acc = fmaf(hp[rr][k], Wg0[k * H1 + f], acc);
    g_support[(size_t)i * H1 + f] = acc;
}

// ================= kernel 4: gnn layer 1 (warp/row, MLP=8, smem weights) ===
__global__ void __launch_bounds__(256)
gnn1_kernel(const float* __restrict__ bg0,
            const float* __restrict__ br) {
    __shared__ int    sidx[8][CAP];
    __shared__ float  shp[8][H1];
    __shared__ float2 scw[H1 * H2];
    int tid = threadIdx.x;
    int lane = tid & 31, wid = tid >> 5;
    int i = blockIdx.x * 8 + wid;

    {
        const float4* src = (const float4*)g_WgC;
        float4* dst = (float4*)scw;
#pragma unroll
        for (int q = 0; q < 4; q++) dst[tid + q * 256] = src[tid + q * 256];
    }

    int total = g_nbr_cnt[i];
    int cnt = min(total, CAP);
    const int* gl = g_nbr_idx + (size_t)i * CAP;
    for (int k = lane; k < cnt; k += 32) sidx[wid][k] = gl[k];
    __syncwarp();

    const float2* sup = (const float2*)g_support;
    float2 a0 = {0.f, 0.f}, a1 = {0.f, 0.f}, a2 = {0.f, 0.f}, a3 = {0.f, 0.f};
    float2 a4 = {0.f, 0.f}, a5 = {0.f, 0.f}, a6 = {0.f, 0.f}, a7 = {0.f, 0.f};
    int k = 0;
    for (; k + 8 <= cnt; k += 8) {
        int4 j0 = *(const int4*)&sidx[wid][k];
        int4 j1 = *(const int4*)&sidx[wid][k + 4];
        float2 p0 = sup[(size_t)j0.x * 32 + lane];
        float2 p1 = sup[(size_t)j0.y * 32 + lane];
        float2 p2 = sup[(size_t)j0.z * 32 + lane];
        float2 p3 = sup[(size_t)j0.w * 32 + lane];
        float2 p4 = sup[(size_t)j1.x * 32 + lane];
        float2 p5 = sup[(size_t)j1.y * 32 + lane];
        float2 p6 = sup[(size_t)j1.z * 32 + lane];
        float2 p7 = sup[(size_t)j1.w * 32 + lane];
        a0.x += p0.x; a0.y += p0.y;  a1.x += p1.x; a1.y += p1.y;
        a2.x += p2.x; a2.y += p2.y;  a3.x += p3.x; a3.y += p3.y;
        a4.x += p4.x; a4.y += p4.y;  a5.x += p5.x; a5.y += p5.y;
        a6.x += p6.x; a6.y += p6.y;  a7.x += p7.x; a7.y += p7.y;
    }
    for (; k + 4 <= cnt; k += 4) {
        int4 j0 = *(const int4*)&sidx[wid][k];
        float2 p0 = sup[(size_t)j0.x * 32 + lane];
        float2 p1 = sup[(size_t)j0.y * 32 + lane];
        float2 p2 = sup[(size_t)j0.z * 32 + lane];
        float2 p3 = sup[(size_t)j0.w * 32 + lane];
        a0.x += p0.x; a0.y += p0.y;  a1.x += p1.x; a1.y += p1.y;
        a2.x += p2.x; a2.y += p2.y;  a3.x += p3.x; a3.y += p3.y;
    }
    for (; k < cnt; k++) {
        float2 p = sup[(size_t)sidx[wid][k] * 32 + lane];
        a0.x += p.x; a0.y += p.y;
    }
    float dinv = 1.f / (float)total;
    float2 bg = ((const float2*)bg0)[lane];
    float2 h;
    h.x = leaky((a0.x + a1.x + a2.x + a3.x + a4.x + a5.x + a6.x + a7.x) * dinv + bg.x);
    h.y = leaky((a0.y + a1.y + a2.y + a3.y + a4.y + a5.y + a6.y + a7.y) * dinv + bg.y);
    *(float2*)&shp[wid][2 * lane] = h;
    __syncthreads();

    float s2 = 0.f, rr2 = 0.f;
#pragma unroll
    for (int kk = 0; kk < H1; kk += 4) {
        float4 hv = *(const float4*)&shp[wid][kk];
        float2 w0 = scw[(kk + 0) * H2 + lane];
        float2 w1 = scw[(kk + 1) * H2 + lane];
        float2 w2 = scw[(kk + 2) * H2 + lane];
        float2 w3 = scw[(kk + 3) * H2 + lane];
        s2  = fmaf(hv.x, w0.x, s2);  rr2 = fmaf(hv.x, w0.y, rr2);
        s2  = fmaf(hv.y, w1.x, s2);  rr2 = fmaf(hv.y, w1.y, rr2);
        s2  = fmaf(hv.z, w2.x, s2);  rr2 = fmaf(hv.z, w2.y, rr2);
        s2  = fmaf(hv.w, w3.x, s2);  rr2 = fmaf(hv.w, w3.y, rr2);
    }
    g_support2[(size_t)i * H2 + lane] = s2;
    g_resid[(size_t)i * H2 + lane]    = rr2 + br[lane];
}

// ================= kernel 5: gnn layer 2 + residual -> out (MLP=16) =======
__global__ void __launch_bounds__(256)
gnn2_kernel(const float* __restrict__ bg1,
            float* __restrict__ out) {
    __shared__ int sidx[8][CAP];
    int tid = threadIdx.x;
    int lane = tid & 31, wid = tid >> 5;
    int i = blockIdx.x * 8 + wid;
    int total = g_nbr_cnt[i];
    int cnt = min(total, CAP);
    const int* gl = g_nbr_idx + (size_t)i * CAP;
    for (int k = lane; k < cnt; k += 32) sidx[wid][k] = gl[k];
    __syncwarp();

    const float* sup2 = g_support2;
    float a0 = 0.f, a1 = 0.f, a2 = 0.f, a3 = 0.f;
    float a4 = 0.f, a5 = 0.f, a6 = 0.f, a7 = 0.f;
    float b0 = 0.f, b1 = 0.f, b2 = 0.f, b3 = 0.f;
    float b4 = 0.f, b5 = 0.f, b6 = 0.f, b7 = 0.f;
    int k = 0;
    for (; k + 16 <= cnt; k += 16) {
        int4 j0 = *(const int4*)&sidx[wid][k];
        int4 j1 = *(const int4*)&sidx[wid][k + 4];
        int4 j2 = *(const int4*)&sidx[wid][k + 8];
        int4 j3 = *(const int4*)&sidx[wid][k + 12];
        a0 += sup2[(size_t)j0.x * H2 + lane];
        a1 += sup2[(size_t)j0.y * H2 + lane];
        a2 += sup2[(size_t)j0.z * H2 + lane];
        a3 += sup2[(size_t)j0.w * H2 + lane];
        a4 += sup2[(size_t)j1.x * H2 + lane];
        a5 += sup2[(size_t)j1.y * H2 + lane];
        a6 += sup2[(size_t)j1.z * H2 + lane];
        a7 += sup2[(size_t)j1.w * H2 + lane];
        b0 += sup2[(size_t)j2.x * H2 + lane];
        b1 += sup2[(size_t)j2.y * H2 + lane];
        b2 += sup2[(size_t)j2.z * H2 + lane];
        b3 += sup2[(size_t)j2.w * H2 + lane];
        b4 += sup2[(size_t)j3.x * H2 + lane];
        b5 += sup2[(size_t)j3.y * H2 + lane];
        b6 += sup2[(size_t)j3.z * H2 + lane];
        b7 += sup2[(size_t)j3.w * H2 + lane];
    }
    for (; k + 4 <= cnt; k += 4) {
        int4 j0 = *(const int4*)&sidx[wid][k];
        a0 += sup2[(size_t)j0.x * H2 + lane];
        a1 += sup2[(size_t)j0.y * H2 + lane];
        a2 += sup2[(size_t)j0.z * H2 + lane];
        a3 += sup2[(size_t)j0.w * H2 + lane];
    }
    for (; k < cnt; k++) a0 += sup2[(size_t)sidx[wid][k] * H2 + lane];

    float agg = (a0 + a1 + a2 + a3 + a4 + a5 + a6 + a7)
              + (b0 + b1 + b2 + b3 + b4 + b5 + b6 + b7);
    float v = leaky(agg * (1.f / (float)total) + bg1[lane]);
    out[(size_t)i * H2 + lane] = v + g_resid[(size_t)i * H2 + lane];
}

extern "C" void kernel_launch(void* const* d_in, const int* in_sizes, int n_in,
                              void* d_out, int out_size) {
    const float* x   = (const float*)d_in[0];
    const float* adj = (const float*)d_in[1];
    const float* W1  = (const float*)d_in[2];
    const float* a1  = (const float*)d_in[3];
    const float* W2  = (const float*)d_in[4];
    const float* a2  = (const float*)d_in[5];
    const float* W3  = (const float*)d_in[6];
    const float* a3  = (const float*)d_in[7];
    const float* Wg0 = (const float*)d_in[8];
    const float* bg0 = (const float*)d_in[9];
    const float* Wg1 = (const float*)d_in[10];
    const float* bg1 = (const float*)d_in[11];
    const float* Wr  = (const float*)d_in[12];
    const float* br  = (const float*)d_in[13];
    const void*  rel = d_in[14];
    float* out = (float*)d_out;

    scanwh_kernel<<<WH_BLOCKS + 3 * N / 2, 256>>>(x, adj, W1, a1, W2, a2, W3, a3);
    attn_kernel<<<3 * N / 2, 256>>>(rel);
    fuse_kernel<<<N / 4, 256>>>(Wg0, Wg1, Wr);
    gnn1_kernel<<<N / 8, 256>>>(bg0, br);
    gnn2_kernel<<<N / 8, 256>>>(bg1, out);
}

// round 15
// speedup vs baseline: 1.0217x; 1.0217x over previous
#include <cuda_runtime.h>
#include <cuda_fp16.h>
#include <math.h>
#include <float.h>

#define N 4096
#define IN_F 256
#define H0 64
#define H1 64
#define H2 32
#define CAP 256
#define SLOPE 0.01f

// -------- scratch (device globals; no allocation) --------
__device__ int    g_nbr_idx[N * CAP];     // only the selected relation
__device__ int    g_nbr_cnt[N];
__device__ __half g_WhH[3 * N * H0];      // fp16 Wh (gather traffic halved)
__device__ float  g_ssrc[3 * N];
__device__ float  g_sdst[3 * N];
__device__ float  g_hr[3 * N * H0];
__device__ float  g_support[N * H1];
__device__ float  g_support2[N * H2];
__device__ float  g_resid[N * H2];
__device__ float2 g_WgC[H1 * H2];          // {Wg1[k][j], Wr[j][k]} combined

__device__ __forceinline__ float leaky(float v) { return v >= 0.f ? v : SLOPE * v; }

__device__ __forceinline__ int read_relation(const void* p) {
    int r = *reinterpret_cast<const int*>(p);
    if (r < 0 || r > 2) {
        float fv = *reinterpret_cast<const float*>(p);
        r = (int)fv;
        if (r < 0 || r > 2) r = 0;
    }
    return r;
}

__device__ __forceinline__ unsigned mask16(float4 v0, float4 v1, float4 v2, float4 v3) {
    unsigned mask = 0;
    if (v0.x > 0.f) mask |= 1u << 0;  if (v0.y > 0.f) mask |= 1u << 1;
    if (v0.z > 0.f) mask |= 1u << 2;  if (v0.w > 0.f) mask |= 1u << 3;
    if (v1.x > 0.f) mask |= 1u << 4;  if (v1.y > 0.f) mask |= 1u << 5;
    if (v1.z > 0.f) mask |= 1u << 6;  if (v1.w > 0.f) mask |= 1u << 7;
    if (v2.x > 0.f) mask |= 1u << 8;  if (v2.y > 0.f) mask |= 1u << 9;
    if (v2.z > 0.f) mask |= 1u << 10; if (v2.w > 0.f) mask |= 1u << 11;
    if (v3.x > 0.f) mask |= 1u << 12; if (v3.y > 0.f) mask |= 1u << 13;
    if (v3.z > 0.f) mask |= 1u << 14; if (v3.w > 0.f) mask |= 1u << 15;
    return mask;
}

// ================= kernel 1: Wh = x @ W_r, s_src, s_dst ===================
__global__ void __launch_bounds__(256)
wh_kernel(const float* __restrict__ x,
          const float* __restrict__ W1, const float* __restrict__ a1,
          const float* __restrict__ W2, const float* __restrict__ a2,
          const float* __restrict__ W3, const float* __restrict__ a3) {
    int r = blockIdx.y;
    int row0 = blockIdx.x * 64;
    const float* W = (r == 0) ? W1 : (r == 1) ? W2 : W3;
    const float* a = (r == 0) ? a1 : (r == 1) ? a2 : a3;
    int tid = threadIdx.x;
    int rg = tid >> 4;
    int cgp = tid & 15;

    __shared__ float sx[64][64];
    __shared__ float sW[64][64];

    float4 acc[4];
#pragma unroll
    for (int q = 0; q < 4; q++) acc[q] = make_float4(0.f, 0.f, 0.f, 0.f);

    for (int k0 = 0; k0 < IN_F; k0 += 64) {
        __syncthreads();
#pragma unroll
        for (int q = 0; q < 4; q++) {
            int lin = tid + q * 256;
            int rr = lin >> 4, c4 = (lin & 15) << 2;
            *(float4*)&sx[rr][c4] = *(const float4*)(x + (size_t)(row0 + rr) * IN_F + k0 + c4);
        }
#pragma unroll
        for (int q = 0; q < 4; q++) {
            int lin = tid + q * 256;
            int kr = lin >> 4, c4 = (lin & 15) << 2;
            *(float4*)&sW[kr][c4] = *(const float4*)(W + (size_t)(k0 + kr) * H0 + c4);
        }
        __syncthreads();
#pragma unroll 16
        for (int kk = 0; kk < 64; kk++) {
            float4 wv = *(float4*)&sW[kk][cgp * 4];
            float xv0 = sx[rg * 4 + 0][kk];
            float xv1 = sx[rg * 4 + 1][kk];
            float xv2 = sx[rg * 4 + 2][kk];
            float xv3 = sx[rg * 4 + 3][kk];
            acc[0].x = fmaf(xv0, wv.x, acc[0].x); acc[0].y = fmaf(xv0, wv.y, acc[0].y);
            acc[0].z = fmaf(xv0, wv.z, acc[0].z); acc[0].w = fmaf(xv0, wv.w, acc[0].w);
            acc[1].x = fmaf(xv1, wv.x, acc[1].x); acc[1].y = fmaf(xv1, wv.y, acc[1].y);
            acc[1].z = fmaf(xv1, wv.z, acc[1].z); acc[1].w = fmaf(xv1, wv.w, acc[1].w);
            acc[2].x = fmaf(xv2, wv.x, acc[2].x); acc[2].y = fmaf(xv2, wv.y, acc[2].y);
            acc[2].z = fmaf(xv2, wv.z, acc[2].z); acc[2].w = fmaf(xv2, wv.w, acc[2].w);
            acc[3].x = fmaf(xv3, wv.x, acc[3].x); acc[3].y = fmaf(xv3, wv.y, acc[3].y);
            acc[3].z = fmaf(xv3, wv.z, acc[3].z); acc[3].w = fmaf(xv3, wv.w, acc[3].w);
        }
    }

    float4 av = *(const float4*)(a + cgp * 4);
    float4 ad = *(const float4*)(a + H0 + cgp * 4);
#pragma unroll
    for (int ri = 0; ri < 4; ri++) {
        int grow = row0 + rg * 4 + ri;
        __half2 h01 = __float22half2_rn(make_float2(acc[ri].x, acc[ri].y));
        __half2 h23 = __float22half2_rn(make_float2(acc[ri].z, acc[ri].w));
        __half2* dst = (__half2*)(g_WhH + ((size_t)r * N + grow) * H0 + cgp * 4);
        dst[0] = h01;
        dst[1] = h23;
        float ps = acc[ri].x * av.x + acc[ri].y * av.y + acc[ri].z * av.z + acc[ri].w * av.w;
        float pd = acc[ri].x * ad.x + acc[ri].y * ad.y + acc[ri].z * ad.z + acc[ri].w * ad.w;
#pragma unroll
        for (int off = 8; off > 0; off >>= 1) {
            ps += __shfl_down_sync(0xffffffffu, ps, off, 16);
            pd += __shfl_down_sync(0xffffffffu, pd, off, 16);
        }
        if (cgp == 0) { g_ssrc[r * N + grow] = ps; g_sdst[r * N + grow] = pd; }
    }
}

// ===== kernel 2: adj scan + softmax + Wh gather (fp16), 2 rows per block ==
__global__ void __launch_bounds__(256)
scan_attn_kernel(const float* __restrict__ adj, const void* __restrict__ relation) {
    __shared__ int      s_idx[2][CAP];
    __shared__ float    s_w[2][CAP];
    __shared__ unsigned s_wsum[8];
    __shared__ float    s_m[2][8];
    __shared__ float    s_s[2][8];
    __shared__ float    s_acc[2][4][H0];

    int b = blockIdx.x;
    int r = b >> 11;
    int i0 = (b & 2047) * 2;
    int id0 = r * N + i0;
    int tid = threadIdx.x;
    int lane = tid & 31, wid = tid >> 5;

    const float4* rowA = (const float4*)(adj + (size_t)id0 * N);
    const float4* rowB = rowA + (N / 4);
    float4 va0 = rowA[tid], va1 = rowA[tid + 256], va2 = rowA[tid + 512], va3 = rowA[tid + 768];
    float4 vb0 = rowB[tid], vb1 = rowB[tid + 256], vb2 = rowB[tid + 512], vb3 = rowB[tid + 768];
    unsigned m0 = mask16(va0, va1, va2, va3);
    unsigned m1 = mask16(vb0, vb1, vb2, vb3);
    unsigned pc = (unsigned)__popc(m0) | ((unsigned)__popc(m1) << 16);

    unsigned pre = pc;
#pragma unroll
    for (int off = 1; off < 32; off <<= 1) {
        unsigned nv = __shfl_up_sync(0xffffffffu, pre, off);
        if (lane >= off) pre += nv;
    }
    if (lane == 31) s_wsum[wid] = pre;
    __syncthreads();
    unsigned wbase = 0, totp = 0;
#pragma unroll
    for (int w = 0; w < 8; w++) {
        unsigned v = s_wsum[w];
        if (w < wid) wbase += v;
        totp += v;
    }
    unsigned startp = wbase + pre - pc;
    int pos0 = startp & 0xFFFFu;
    int pos1 = startp >> 16;
    int total0 = totp & 0xFFFFu;
    int total1 = totp >> 16;

    {
        unsigned mm = m0;
        int pos = pos0;
        while (mm) {
            int bb = __ffs(mm) - 1;
            mm &= mm - 1;
            int q = bb >> 2, j = bb & 3;
            int col = ((tid + (q << 8)) << 2) + j;
            if (pos < CAP) s_idx[0][pos] = col;
            pos++;
        }
        mm = m1;
        pos = pos1;
        while (mm) {
            int bb = __ffs(mm) - 1;
            mm &= mm - 1;
            int q = bb >> 2, j = bb & 3;
            int col = ((tid + (q << 8)) << 2) + j;
            if (pos < CAP) s_idx[1][pos] = col;
            pos++;
        }
    }
    __syncthreads();
    int cnt0 = min(total0, CAP);
    int cnt1 = min(total1, CAP);

    int relv = read_relation(relation);
    if (r == relv) {
        int* gl0 = g_nbr_idx + (size_t)i0 * CAP;
        int* gl1 = gl0 + CAP;
        for (int k = tid; k < cnt0; k += 256) gl0[k] = s_idx[0][k];
        for (int k = tid; k < cnt1; k += 256) gl1[k] = s_idx[1][k];
        if (tid == 0) { g_nbr_cnt[i0] = total0; g_nbr_cnt[i0 + 1] = total1; }
    }

    float si0 = g_ssrc[id0];
    float si1 = g_ssrc[id0 + 1];
    const float* sdstR = g_sdst + r * N;
    float sc0 = (tid < cnt0) ? leaky(si0 + sdstR[s_idx[0][tid]]) : -FLT_MAX;
    float sc1 = (tid < cnt1) ? leaky(si1 + sdstR[s_idx[1][tid]]) : -FLT_MAX;

    float mm0 = sc0, mm1 = sc1;
#pragma unroll
    for (int off = 16; off > 0; off >>= 1) {
        mm0 = fmaxf(mm0, __shfl_xor_sync(0xffffffffu, mm0, off));
        mm1 = fmaxf(mm1, __shfl_xor_sync(0xffffffffu, mm1, off));
    }
    if (lane == 0) { s_m[0][wid] = mm0; s_m[1][wid] = mm1; }
    __syncthreads();
    float bm0 = s_m[0][0], bm1 = s_m[1][0];
#pragma unroll
    for (int w = 1; w < 8; w++) {
        bm0 = fmaxf(bm0, s_m[0][w]);
        bm1 = fmaxf(bm1, s_m[1][w]);
    }

    float e0 = (tid < cnt0) ? __expf(sc0 - bm0) : 0.f;
    float e1 = (tid < cnt1) ? __expf(sc1 - bm1) : 0.f;
    s_w[0][tid] = e0;
    s_w[1][tid] = e1;
    float su0 = e0, su1 = e1;
#pragma unroll
    for (int off = 16; off > 0; off >>= 1) {
        su0 += __shfl_xor_sync(0xffffffffu, su0, off);
        su1 += __shfl_xor_sync(0xffffffffu, su1, off);
    }
    if (lane == 0) { s_s[0][wid] = su0; s_s[1][wid] = su1; }
    __syncthreads();
    float bs0 = s_s[0][0], bs1 = s_s[1][0];
#pragma unroll
    for (int w = 1; w < 8; w++) { bs0 += s_s[0][w]; bs1 += s_s[1][w]; }
    float inv0 = 1.f / bs0;
    float inv1 = 1.f / bs1;

    int f = tid & 63;
    int kc = tid >> 6;
    const __half* WhR = g_WhH + (size_t)r * N * H0;
    float acc0 = 0.f, acc1 = 0.f;
    int k = kc;
    for (; k + 12 < cnt0; k += 16) {
        int j0 = s_idx[0][k], j1 = s_idx[0][k + 4], j2 = s_idx[0][k + 8], j3 = s_idx[0][k + 12];
        float w0 = s_w[0][k], w1 = s_w[0][k + 4], w2 = s_w[0][k + 8], w3 = s_w[0][k + 12];
        float p0 = __half2float(WhR[(size_t)j0 * H0 + f]);
        float p1 = __half2float(WhR[(size_t)j1 * H0 + f]);
        float p2 = __half2float(WhR[(size_t)j2 * H0 + f]);
        float p3 = __half2float(WhR[(size_t)j3 * H0 + f]);
        acc0 = fmaf(w0, p0, acc0);
        acc0 = fmaf(w1, p1, acc0);
        acc0 = fmaf(w2, p2, acc0);
        acc0 = fmaf(w3, p3, acc0);
    }
    for (; k < cnt0; k += 4)
        acc0 = fmaf(s_w[0][k], __half2float(WhR[(size_t)s_idx[0][k] * H0 + f]), acc0);
    k = kc;
    for (; k + 12 < cnt1; k += 16) {
        int j0 = s_idx[1][k], j1 = s_idx[1][k + 4], j2 = s_idx[1][k + 8], j3 = s_idx[1][k + 12];
        float w0 = s_w[1][k], w1 = s_w[1][k + 4], w2 = s_w[1][k + 8], w3 = s_w[1][k + 12];
        float p0 = __half2float(WhR[(size_t)j0 * H0 + f]);
        float p1 = __half2float(WhR[(size_t)j1 * H0 + f]);
        float p2 = __half2float(WhR[(size_t)j2 * H0 + f]);
        float p3 = __half2float(WhR[(size_t)j3 * H0 + f]);
        acc1 = fmaf(w0, p0, acc1);
        acc1 = fmaf(w1, p1, acc1);
        acc1 = fmaf(w2, p2, acc1);
        acc1 = fmaf(w3, p3, acc1);
    }
    for (; k < cnt1; k += 4)
        acc1 = fmaf(s_w[1][k], __half2float(WhR[(size_t)s_idx[1][k] * H0 + f]), acc1);
    s_acc[0][kc][f] = acc0;
    s_acc[1][kc][f] = acc1;
    __syncthreads();
    if (tid < 128) {
        int rr = tid >> 6, f2 = tid & 63;
        float inv = rr ? inv1 : inv0;
        float o = (s_acc[rr][0][f2] + s_acc[rr][1][f2] + s_acc[rr][2][f2] + s_acc[rr][3][f2]) * inv;
        g_hr[(size_t)(id0 + rr) * H0 + f2] = o;
    }
}

// ================= kernel 3: fuse + support + combined-weight prep ========
__global__ void __launch_bounds__(256)
fuse_kernel(const float* __restrict__ Wg0, const float* __restrict__ Wg1,
            const float* __restrict__ Wr) {
    int tid = threadIdx.x;
    int rr = tid >> 6;
    int f = tid & 63;
    int i = blockIdx.x * 4 + rr;
    if (blockIdx.x == 0) {
#pragma unroll
        for (int t = tid; t < H1 * H2; t += 256) {
            int k = t >> 5, j = t & 31;
            g_WgC[t] = make_float2(Wg1[k * H2 + j], Wr[j * H1 + k]);
        }
    }
    __shared__ float hp[4][H0];
    float v = (g_hr[(size_t)i * H0 + f] +
               g_hr[((size_t)N + i) * H0 + f] +
               g_hr[((size_t)2 * N + i) * H0 + f]) * (1.f / 3.f);
    hp[rr][f] = 1.f / (1.f + __expf(-v));
    __syncthreads();
    float acc = 0.f;
#pragma unroll 16
    for (int k = 0; k < H0; k++) acc = fmaf(hp[rr][k], Wg0[k * H1 + f], acc);
    g_support[(size_t)i * H1 + f] = acc;
}

// ============ kernel 4: gnn layer 1 (warp/row, MLP=16, smem weights) ======
__global__ void __launch_bounds__(256)
gnn1_kernel(const float* __restrict__ bg0,
            const float* __restrict__ br) {
    __shared__ int    sidx[8][CAP];
    __shared__ float  shp[8][H1];
    __shared__ float2 scw[H1 * H2];
    int tid = threadIdx.x;
    int lane = tid & 31, wid = tid >> 5;
    int i = blockIdx.x * 8 + wid;

    {
        const float4* src = (const float4*)g_WgC;
        float4* dst = (float4*)scw;
#pragma unroll
        for (int q = 0; q < 4; q++) dst[tid + q * 256] = src[tid + q * 256];
    }

    int total = g_nbr_cnt[i];
    int cnt = min(total, CAP);
    const int* gl = g_nbr_idx + (size_t)i * CAP;
    for (int k = lane; k < cnt; k += 32) sidx[wid][k] = gl[k];
    __syncwarp();

    const float2* sup = (const float2*)g_support;
    float2 a0 = {0.f, 0.f}, a1 = {0.f, 0.f}, a2 = {0.f, 0.f}, a3 = {0.f, 0.f};
    float2 a4 = {0.f, 0.f}, a5 = {0.f, 0.f}, a6 = {0.f, 0.f}, a7 = {0.f, 0.f};
    float2 b0 = {0.f, 0.f}, b1 = {0.f, 0.f}, b2 = {0.f, 0.f}, b3 = {0.f, 0.f};
    float2 b4 = {0.f, 0.f}, b5 = {0.f, 0.f}, b6 = {0.f, 0.f}, b7 = {0.f, 0.f};
    int k = 0;
    for (; k + 16 <= cnt; k += 16) {
        int4 j0 = *(const int4*)&sidx[wid][k];
        int4 j1 = *(const int4*)&sidx[wid][k + 4];
        int4 j2 = *(const int4*)&sidx[wid][k + 8];
        int4 j3 = *(const int4*)&sidx[wid][k + 12];
        float2 p0 = sup[(size_t)j0.x * 32 + lane];
        float2 p1 = sup[(size_t)j0.y * 32 + lane];
        float2 p2 = sup[(size_t)j0.z * 32 + lane];
        float2 p3 = sup[(size_t)j0.w * 32 + lane];
        float2 p4 = sup[(size_t)j1.x * 32 + lane];
        float2 p5 = sup[(size_t)j1.y * 32 + lane];
        float2 p6 = sup[(size_t)j1.z * 32 + lane];
        float2 p7 = sup[(size_t)j1.w * 32 + lane];
        float2 q0 = sup[(size_t)j2.x * 32 + lane];
        float2 q1 = sup[(size_t)j2.y * 32 + lane];
        float2 q2 = sup[(size_t)j2.z * 32 + lane];
        float2 q3 = sup[(size_t)j2.w * 32 + lane];
        float2 q4 = sup[(size_t)j3.x * 32 + lane];
        float2 q5 = sup[(size_t)j3.y * 32 + lane];
        float2 q6 = sup[(size_t)j3.z * 32 + lane];
        float2 q7 = sup[(size_t)j3.w * 32 + lane];
        a0.x += p0.x; a0.y += p0.y;  a1.x += p1.x; a1.y += p1.y;
        a2.x += p2.x; a2.y += p2.y;  a3.x += p3.x; a3.y += p3.y;
        a4.x += p4.x; a4.y += p4.y;  a5.x += p5.x; a5.y += p5.y;
        a6.x += p6.x; a6.y += p6.y;  a7.x += p7.x; a7.y += p7.y;
        b0.x += q0.x; b0.y += q0.y;  b1.x += q1.x; b1.y += q1.y;
        b2.x += q2.x; b2.y += q2.y;  b3.x += q3.x; b3.y += q3.y;
        b4.x += q4.x; b4.y += q4.y;  b5.x += q5.x; b5.y += q5.y;
        b6.x += q6.x; b6.y += q6.y;  b7.x += q7.x; b7.y += q7.y;
    }
    for (; k + 8 <= cnt; k += 8) {
        int4 j0 = *(const int4*)&sidx[wid][k];
        int4 j1 = *(const int4*)&sidx[wid][k + 4];
        float2 p0 = sup[(size_t)j0.x * 32 + lane];
        float2 p1 = sup[(size_t)j0.y * 32 + lane];
        float2 p2 = sup[(size_t)j0.z * 32 + lane];
        float2 p3 = sup[(size_t)j0.w * 32 + lane];
        float2 p4 = sup[(size_t)j1.x * 32 + lane];
        float2 p5 = sup[(size_t)j1.y * 32 + lane];
        float2 p6 = sup[(size_t)j1.z * 32 + lane];
        float2 p7 = sup[(size_t)j1.w * 32 + lane];
        a0.x += p0.x; a0.y += p0.y;  a1.x += p1.x; a1.y += p1.y;
        a2.x += p2.x; a2.y += p2.y;  a3.x += p3.x; a3.y += p3.y;
        a4.x += p4.x; a4.y += p4.y;  a5.x += p5.x; a5.y += p5.y;
        a6.x += p6.x; a6.y += p6.y;  a7.x += p7.x; a7.y += p7.y;
    }
    for (; k + 4 <= cnt; k += 4) {
        int4 j0 = *(const int4*)&sidx[wid][k];
        float2 p0 = sup[(size_t)j0.x * 32 + lane];
        float2 p1 = sup[(size_t)j0.y * 32 + lane];
        float2 p2 = sup[(size_t)j0.z * 32 + lane];
        float2 p3 = sup[(size_t)j0.w * 32 + lane];
        a0.x += p0.x; a0.y += p0.y;  a1.x += p1.x; a1.y += p1.y;
        a2.x += p2.x; a2.y += p2.y;  a3.x += p3.x; a3.y += p3.y;
    }
    for (; k < cnt; k++) {
        float2 p = sup[(size_t)sidx[wid][k] * 32 + lane];
        a0.x += p.x; a0.y += p.y;
    }
    float dinv = 1.f / (float)total;
    float2 bg = ((const float2*)bg0)[lane];
    float sx = (a0.x + a1.x + a2.x + a3.x) + (a4.x + a5.x + a6.x + a7.x)
             + (b0.x + b1.x + b2.x + b3.x) + (b4.x + b5.x + b6.x + b7.x);
    float sy = (a0.y + a1.y + a2.y + a3.y) + (a4.y + a5.y + a6.y + a7.y)
             + (b0.y + b1.y + b2.y + b3.y) + (b4.y + b5.y + b6.y + b7.y);
    float2 h;
    h.x = leaky(sx * dinv + bg.x);
    h.y = leaky(sy * dinv + bg.y);
    *(float2*)&shp[wid][2 * lane] = h;
    __syncthreads();

    float s2 = 0.f, rr2 = 0.f;
#pragma unroll
    for (int kk = 0; kk < H1; kk += 4) {
        float4 hv = *(const float4*)&shp[wid][kk];
        float2 w0 = scw[(kk + 0) * H2 + lane];
        float2 w1 = scw[(kk + 1) * H2 + lane];
        float2 w2 = scw[(kk + 2) * H2 + lane];
        float2 w3 = scw[(kk + 3) * H2 + lane];
        s2  = fmaf(hv.x, w0.x, s2);  rr2 = fmaf(hv.x, w0.y, rr2);
        s2  = fmaf(hv.y, w1.x, s2);  rr2 = fmaf(hv.y, w1.y, rr2);
        s2  = fmaf(hv.z, w2.x, s2);  rr2 = fmaf(hv.z, w2.y, rr2);
        s2  = fmaf(hv.w, w3.x, s2);  rr2 = fmaf(hv.w, w3.y, rr2);
    }
    g_support2[(size_t)i * H2 + lane] = s2;
    g_resid[(size_t)i * H2 + lane]    = rr2 + br[lane];
}

// ================= kernel 5: gnn layer 2 + residual -> out (MLP=32) =======
__global__ void __launch_bounds__(256)
gnn2_kernel(const float* __restrict__ bg1,
            float* __restrict__ out) {
    __shared__ int sidx[8][CAP];
    int tid = threadIdx.x;
    int lane = tid & 31, wid = tid >> 5;
    int i = blockIdx.x * 8 + wid;
    int total = g_nbr_cnt[i];
    int cnt = min(total, CAP);
    const int* gl = g_nbr_idx + (size_t)i * CAP;
    for (int k = lane; k < cnt; k += 32) sidx[wid][k] = gl[k];
    __syncwarp();

    const float* sup2 = g_support2;
    float a[16];
    float b[16];
#pragma unroll
    for (int t = 0; t < 16; t++) { a[t] = 0.f; b[t] = 0.f; }
    int k = 0;
    for (; k + 32 <= cnt; k += 32) {
#pragma unroll
        for (int g = 0; g < 4; g++) {
            int4 j0 = *(const int4*)&sidx[wid][k + g * 8];
            int4 j1 = *(const int4*)&sidx[wid][k + g * 8 + 4];
            a[g * 4 + 0] += sup2[(size_t)j0.x * H2 + lane];
            a[g * 4 + 1] += sup2[(size_t)j0.y * H2 + lane];
            a[g * 4 + 2] += sup2[(size_t)j0.z * H2 + lane];
            a[g * 4 + 3] += sup2[(size_t)j0.w * H2 + lane];
            b[g * 4 + 0] += sup2[(size_t)j1.x * H2 + lane];
            b[g * 4 + 1] += sup2[(size_t)j1.y * H2 + lane];
            b[g * 4 + 2] += sup2[(size_t)j1.z * H2 + lane];
            b[g * 4 + 3] += sup2[(size_t)j1.w * H2 + lane];
        }
    }
    for (; k + 16 <= cnt; k += 16) {
#pragma unroll
        for (int g = 0; g < 2; g++) {
            int4 j0 = *(const int4*)&sidx[wid][k + g * 8];
            int4 j1 = *(const int4*)&sidx[wid][k + g * 8 + 4];
            a[g * 4 + 0] += sup2[(size_t)j0.x * H2 + lane];
            a[g * 4 + 1] += sup2[(size_t)j0.y * H2 + lane];
            a[g * 4 + 2] += sup2[(size_t)j0.z * H2 + lane];
            a[g * 4 + 3] += sup2[(size_t)j0.w * H2 + lane];
            b[g * 4 + 0] += sup2[(size_t)j1.x * H2 + lane];
            b[g * 4 + 1] += sup2[(size_t)j1.y * H2 + lane];
            b[g * 4 + 2] += sup2[(size_t)j1.z * H2 + lane];
            b[g * 4 + 3] += sup2[(size_t)j1.w * H2 + lane];
        }
    }
    for (; k + 4 <= cnt; k += 4) {
        int4 j0 = *(const int4*)&sidx[wid][k];
        a[0] += sup2[(size_t)j0.x * H2 + lane];
        a[1] += sup2[(size_t)j0.y * H2 + lane];
        a[2] += sup2[(size_t)j0.z * H2 + lane];
        a[3] += sup2[(size_t)j0.w * H2 + lane];
    }
    for (; k < cnt; k++) a[0] += sup2[(size_t)sidx[wid][k] * H2 + lane];

    float agg = 0.f;
#pragma unroll
    for (int t = 0; t < 16; t++) agg += a[t] + b[t];
    float v = leaky(agg * (1.f / (float)total) + bg1[lane]);
    out[(size_t)i * H2 + lane] = v + g_resid[(size_t)i * H2 + lane];
}

extern "C" void kernel_launch(void* const* d_in, const int* in_sizes, int n_in,
                              void* d_out, int out_size) {
    const float* x   = (const float*)d_in[0];
    const float* adj = (const float*)d_in[1];
    const float* W1  = (const float*)d_in[2];
    const float* a1  = (const float*)d_in[3];
    const float* W2  = (const float*)d_in[4];
    const float* a2  = (const float*)d_in[5];
    const float* W3  = (const float*)d_in[6];
    const float* a3  = (const float*)d_in[7];
    const float* Wg0 = (const float*)d_in[8];
    const float* bg0 = (const float*)d_in[9];
    const float* Wg1 = (const float*)d_in[10];
    const float* bg1 = (const float*)d_in[11];
    const float* Wr  = (const float*)d_in[12];
    const float* br  = (const float*)d_in[13];
    const void*  rel = d_in[14];
    float* out = (float*)d_out;

    wh_kernel<<<dim3(64, 3), 256>>>(x, W1, a1, W2, a2, W3, a3);
    scan_attn_kernel<<<3 * N / 2, 256>>>(adj, rel);
    fuse_kernel<<<N / 4, 256>>>(Wg0, Wg1, Wr);
    gnn1_kernel<<<N / 8, 256>>>(bg0, br);
    gnn2_kernel<<<N / 8, 256>>>(bg1, out);
}

// round 16
// speedup vs baseline: 1.0750x; 1.0522x over previous
#include <cuda_runtime.h>
#include <cuda_fp16.h>
#include <math.h>
#include <float.h>

#define N 4096
#define IN_F 256
#define H0 64
#define H1 64
#define H2 32
#define CAP 256
#define SLOPE 0.01f

// -------- scratch (device globals; no allocation) --------
__device__ int    g_nbr_idx[N * CAP];     // only the selected relation
__device__ int    g_nbr_cnt[N];
__device__ __half g_WhH[3 * N * H0];      // fp16 Wh (gather traffic halved)
__device__ float  g_ssrc[3 * N];
__device__ float  g_sdst[3 * N];
__device__ float  g_support[N * H1];
__device__ float  g_support2[N * H2];
__device__ float  g_resid[N * H2];
__device__ float2 g_WgC[H1 * H2];          // {Wg1[k][j], Wr[j][k]} combined

__device__ __forceinline__ float leaky(float v) { return v >= 0.f ? v : SLOPE * v; }

__device__ __forceinline__ int read_relation(const void* p) {
    int r = *reinterpret_cast<const int*>(p);
    if (r < 0 || r > 2) {
        float fv = *reinterpret_cast<const float*>(p);
        r = (int)fv;
        if (r < 0 || r > 2) r = 0;
    }
    return r;
}

__device__ __forceinline__ unsigned mask16(float4 v0, float4 v1, float4 v2, float4 v3) {
    unsigned mask = 0;
    if (v0.x > 0.f) mask |= 1u << 0;  if (v0.y > 0.f) mask |= 1u << 1;
    if (v0.z > 0.f) mask |= 1u << 2;  if (v0.w > 0.f) mask |= 1u << 3;
    if (v1.x > 0.f) mask |= 1u << 4;  if (v1.y > 0.f) mask |= 1u << 5;
    if (v1.z > 0.f) mask |= 1u << 6;  if (v1.w > 0.f) mask |= 1u << 7;
    if (v2.x > 0.f) mask |= 1u << 8;  if (v2.y > 0.f) mask |= 1u << 9;
    if (v2.z > 0.f) mask |= 1u << 10; if (v2.w > 0.f) mask |= 1u << 11;
    if (v3.x > 0.f) mask |= 1u << 12; if (v3.y > 0.f) mask |= 1u << 13;
    if (v3.z > 0.f) mask |= 1u << 14; if (v3.w > 0.f) mask |= 1u << 15;
    return mask;
}

// ================= kernel 1: Wh = x @ W_r, s_src, s_dst (+WgC prep) =======
__global__ void __launch_bounds__(256)
wh_kernel(const float* __restrict__ x,
          const float* __restrict__ W1, const float* __restrict__ a1,
          const float* __restrict__ W2, const float* __restrict__ a2,
          const float* __restrict__ W3, const float* __restrict__ a3,
          const float* __restrict__ Wg1, const float* __restrict__ Wr) {
    int r = blockIdx.y;
    int row0 = blockIdx.x * 64;
    const float* W = (r == 0) ? W1 : (r == 1) ? W2 : W3;
    const float* a = (r == 0) ? a1 : (r == 1) ? a2 : a3;
    int tid = threadIdx.x;
    int rg = tid >> 4;
    int cgp = tid & 15;

    if (blockIdx.x == 0 && r == 0) {
        // WgC[k*32+j] = { Wg1[k][j], Wr[j][k] } (consumed by gnn1)
#pragma unroll
        for (int t = tid; t < H1 * H2; t += 256) {
            int k = t >> 5, j = t & 31;
            g_WgC[t] = make_float2(Wg1[k * H2 + j], Wr[j * H1 + k]);
        }
    }

    __shared__ float sx[64][64];
    __shared__ float sW[64][64];

    float4 acc[4];
#pragma unroll
    for (int q = 0; q < 4; q++) acc[q] = make_float4(0.f, 0.f, 0.f, 0.f);

    for (int k0 = 0; k0 < IN_F; k0 += 64) {
        __syncthreads();
#pragma unroll
        for (int q = 0; q < 4; q++) {
            int lin = tid + q * 256;
            int rr = lin >> 4, c4 = (lin & 15) << 2;
            *(float4*)&sx[rr][c4] = *(const float4*)(x + (size_t)(row0 + rr) * IN_F + k0 + c4);
        }
#pragma unroll
        for (int q = 0; q < 4; q++) {
            int lin = tid + q * 256;
            int kr = lin >> 4, c4 = (lin & 15) << 2;
            *(float4*)&sW[kr][c4] = *(const float4*)(W + (size_t)(k0 + kr) * H0 + c4);
        }
        __syncthreads();
#pragma unroll 16
        for (int kk = 0; kk < 64; kk++) {
            float4 wv = *(float4*)&sW[kk][cgp * 4];
            float xv0 = sx[rg * 4 + 0][kk];
            float xv1 = sx[rg * 4 + 1][kk];
            float xv2 = sx[rg * 4 + 2][kk];
            float xv3 = sx[rg * 4 + 3][kk];
            acc[0].x = fmaf(xv0, wv.x, acc[0].x); acc[0].y = fmaf(xv0, wv.y, acc[0].y);
            acc[0].z = fmaf(xv0, wv.z, acc[0].z); acc[0].w = fmaf(xv0, wv.w, acc[0].w);
            acc[1].x = fmaf(xv1, wv.x, acc[1].x); acc[1].y = fmaf(xv1, wv.y, acc[1].y);
            acc[1].z = fmaf(xv1, wv.z, acc[1].z); acc[1].w = fmaf(xv1, wv.w, acc[1].w);
            acc[2].x = fmaf(xv2, wv.x, acc[2].x); acc[2].y = fmaf(xv2, wv.y, acc[2].y);
            acc[2].z = fmaf(xv2, wv.z, acc[2].z); acc[2].w = fmaf(xv2, wv.w, acc[2].w);
            acc[3].x = fmaf(xv3, wv.x, acc[3].x); acc[3].y = fmaf(xv3, wv.y, acc[3].y);
            acc[3].z = fmaf(xv3, wv.z, acc[3].z); acc[3].w = fmaf(xv3, wv.w, acc[3].w);
        }
    }

    float4 av = *(const float4*)(a + cgp * 4);
    float4 ad = *(const float4*)(a + H0 + cgp * 4);
#pragma unroll
    for (int ri = 0; ri < 4; ri++) {
        int grow = row0 + rg * 4 + ri;
        __half2 h01 = __float22half2_rn(make_float2(acc[ri].x, acc[ri].y));
        __half2 h23 = __float22half2_rn(make_float2(acc[ri].z, acc[ri].w));
        __half2* dst = (__half2*)(g_WhH + ((size_t)r * N + grow) * H0 + cgp * 4);
        dst[0] = h01;
        dst[1] = h23;
        float ps = acc[ri].x * av.x + acc[ri].y * av.y + acc[ri].z * av.z + acc[ri].w * av.w;
        float pd = acc[ri].x * ad.x + acc[ri].y * ad.y + acc[ri].z * ad.z + acc[ri].w * ad.w;
#pragma unroll
        for (int off = 8; off > 0; off >>= 1) {
            ps += __shfl_down_sync(0xffffffffu, ps, off, 16);
            pd += __shfl_down_sync(0xffffffffu, pd, off, 16);
        }
        if (cgp == 0) { g_ssrc[r * N + grow] = ps; g_sdst[r * N + grow] = pd; }
    }
}

// == kernel 2: 3-relation scan + softmax + gather + sigmoid-fuse + support ==
// One block per row i. 12 float4 loads in flight. Fuse computed in-block:
// no g_hr round-trip, no separate fuse kernel.
__global__ void __launch_bounds__(256)
scan_attn_fuse_kernel(const float* __restrict__ adj,
                      const void* __restrict__ relation,
                      const float* __restrict__ Wg0) {
    __shared__ int      s_idx[3][CAP];
    __shared__ float    s_w[3][CAP];
    __shared__ unsigned long long s_wsum[8];
    __shared__ float    s_m[3][8];
    __shared__ float    s_s[3][8];
    __shared__ float    s_acc[3][4][H0];
    __shared__ float    s_hp[H0];
    __shared__ float    s_part[4][H0];

    int i = blockIdx.x;
    int tid = threadIdx.x;
    int lane = tid & 31, wid = tid >> 5;

    // --- coalesced scan of this row in all 3 relations
    const float4* r0p = (const float4*)(adj + (size_t)i * N);
    const float4* r1p = (const float4*)(adj + ((size_t)N + i) * N);
    const float4* r2p = (const float4*)(adj + ((size_t)2 * N + i) * N);
    unsigned m0, m1, m2;
    {
        float4 a0 = r0p[tid], a1v = r0p[tid + 256], a2v = r0p[tid + 512], a3v = r0p[tid + 768];
        float4 b0 = r1p[tid], b1v = r1p[tid + 256], b2v = r1p[tid + 512], b3v = r1p[tid + 768];
        float4 c0 = r2p[tid], c1v = r2p[tid + 256], c2v = r2p[tid + 512], c3v = r2p[tid + 768];
        m0 = mask16(a0, a1v, a2v, a3v);
        m1 = mask16(b0, b1v, b2v, b3v);
        m2 = mask16(c0, c1v, c2v, c3v);
    }
    unsigned long long pc = (unsigned long long)__popc(m0)
                          | ((unsigned long long)__popc(m1) << 21)
                          | ((unsigned long long)__popc(m2) << 42);

    unsigned long long pre = pc;
#pragma unroll
    for (int off = 1; off < 32; off <<= 1) {
        unsigned long long nv = __shfl_up_sync(0xffffffffu, pre, off);
        if (lane >= off) pre += nv;
    }
    if (lane == 31) s_wsum[wid] = pre;
    __syncthreads();
    unsigned long long wbase = 0, totp = 0;
#pragma unroll
    for (int w = 0; w < 8; w++) {
        unsigned long long v = s_wsum[w];
        if (w < wid) wbase += v;
        totp += v;
    }
    unsigned long long startp = wbase + pre - pc;
    int pos[3], total[3], cnt[3];
    unsigned msk[3] = {m0, m1, m2};
#pragma unroll
    for (int r = 0; r < 3; r++) {
        pos[r]   = (int)((startp >> (21 * r)) & 0x1FFFFFull);
        total[r] = (int)((totp   >> (21 * r)) & 0x1FFFFFull);
        cnt[r]   = min(total[r], CAP);
    }

    // compaction (3 relations)
#pragma unroll
    for (int r = 0; r < 3; r++) {
        unsigned mm = msk[r];
        int p = pos[r];
        while (mm) {
            int bb = __ffs(mm) - 1;
            mm &= mm - 1;
            int q = bb >> 2, j = bb & 3;
            int col = ((tid + (q << 8)) << 2) + j;
            if (p < CAP) s_idx[r][p] = col;
            p++;
        }
    }
    __syncthreads();

    // persist list only for the relation the GNN layers use
    int relv = read_relation(relation);
    {
        int* gl = g_nbr_idx + (size_t)i * CAP;
        int c = cnt[relv];
        const int* src = s_idx[relv];
        for (int k = tid; k < c; k += 256) gl[k] = src[k];
        if (tid == 0) g_nbr_cnt[i] = total[relv];
    }

    // --- scores + softmax (3 relations, shuffles batched)
    float sc[3];
#pragma unroll
    for (int r = 0; r < 3; r++) {
        float si = g_ssrc[r * N + i];
        sc[r] = (tid < cnt[r]) ? leaky(si + g_sdst[r * N + s_idx[r][tid]]) : -FLT_MAX;
    }
    float mm[3] = {sc[0], sc[1], sc[2]};
#pragma unroll
    for (int off = 16; off > 0; off >>= 1) {
        mm[0] = fmaxf(mm[0], __shfl_xor_sync(0xffffffffu, mm[0], off));
        mm[1] = fmaxf(mm[1], __shfl_xor_sync(0xffffffffu, mm[1], off));
        mm[2] = fmaxf(mm[2], __shfl_xor_sync(0xffffffffu, mm[2], off));
    }
    if (lane == 0) { s_m[0][wid] = mm[0]; s_m[1][wid] = mm[1]; s_m[2][wid] = mm[2]; }
    __syncthreads();
    float bm[3] = {s_m[0][0], s_m[1][0], s_m[2][0]};
#pragma unroll
    for (int w = 1; w < 8; w++) {
        bm[0] = fmaxf(bm[0], s_m[0][w]);
        bm[1] = fmaxf(bm[1], s_m[1][w]);
        bm[2] = fmaxf(bm[2], s_m[2][w]);
    }
    float su[3];
#pragma unroll
    for (int r = 0; r < 3; r++) {
        float e = (tid < cnt[r]) ? __expf(sc[r] - bm[r]) : 0.f;
        s_w[r][tid] = e;
        su[r] = e;
    }
#pragma unroll
    for (int off = 16; off > 0; off >>= 1) {
        su[0] += __shfl_xor_sync(0xffffffffu, su[0], off);
        su[1] += __shfl_xor_sync(0xffffffffu, su[1], off);
        su[2] += __shfl_xor_sync(0xffffffffu, su[2], off);
    }
    if (lane == 0) { s_s[0][wid] = su[0]; s_s[1][wid] = su[1]; s_s[2][wid] = su[2]; }
    __syncthreads();
    float inv[3];
#pragma unroll
    for (int r = 0; r < 3; r++) {
        float bs = s_s[r][0];
#pragma unroll
        for (int w = 1; w < 8; w++) bs += s_s[r][w];
        inv[r] = 1.f / bs;
    }

    // --- weighted gathers (fp16 Wh, 4 k-chunks x 64 features per relation)
    int f = tid & 63;
    int kc = tid >> 6;
#pragma unroll
    for (int r = 0; r < 3; r++) {
        const __half* WhR = g_WhH + (size_t)r * N * H0;
        float acc = 0.f;
        int k = kc;
        int c = cnt[r];
        for (; k + 12 < c; k += 16) {
            int j0 = s_idx[r][k], j1 = s_idx[r][k + 4], j2 = s_idx[r][k + 8], j3 = s_idx[r][k + 12];
            float w0 = s_w[r][k], w1 = s_w[r][k + 4], w2 = s_w[r][k + 8], w3 = s_w[r][k + 12];
            float p0 = __half2float(WhR[(size_t)j0 * H0 + f]);
            float p1 = __half2float(WhR[(size_t)j1 * H0 + f]);
            float p2 = __half2float(WhR[(size_t)j2 * H0 + f]);
            float p3 = __half2float(WhR[(size_t)j3 * H0 + f]);
            acc = fmaf(w0, p0, acc);
            acc = fmaf(w1, p1, acc);
            acc = fmaf(w2, p2, acc);
            acc = fmaf(w3, p3, acc);
        }
        for (; k < c; k += 4)
            acc = fmaf(s_w[r][k], __half2float(WhR[(size_t)s_idx[r][k] * H0 + f]), acc);
        s_acc[r][kc][f] = acc;
    }
    __syncthreads();

    // --- fuse: sigmoid(mean of 3) in-block
    if (tid < H0) {
        float h0 = (s_acc[0][0][tid] + s_acc[0][1][tid] + s_acc[0][2][tid] + s_acc[0][3][tid]) * inv[0];
        float h1 = (s_acc[1][0][tid] + s_acc[1][1][tid] + s_acc[1][2][tid] + s_acc[1][3][tid]) * inv[1];
        float h2 = (s_acc[2][0][tid] + s_acc[2][1][tid] + s_acc[2][2][tid] + s_acc[2][3][tid]) * inv[2];
        float v = (h0 + h1 + h2) * (1.f / 3.f);
        s_hp[tid] = 1.f / (1.f + __expf(-v));
    }
    __syncthreads();

    // --- support = h' @ Wg0 (k split 4 ways across 256 threads)
    {
        float partial = 0.f;
        int kbeg = kc * 16;
#pragma unroll 16
        for (int k = 0; k < 16; k++)
            partial = fmaf(s_hp[kbeg + k], Wg0[(kbeg + k) * H1 + f], partial);
        s_part[kc][f] = partial;
    }
    __syncthreads();
    if (tid < H0) {
        g_support[(size_t)i * H1 + tid] =
            s_part[0][tid] + s_part[1][tid] + s_part[2][tid] + s_part[3][tid];
    }
}

// ================= kernel 3: gnn layer 1 (warp/row, MLP=8, smem weights) ===
__global__ void __launch_bounds__(256)
gnn1_kernel(const float* __restrict__ bg0,
            const float* __restrict__ br) {
    __shared__ int    sidx[8][CAP];
    __shared__ float  shp[8][H1];
    __shared__ float2 scw[H1 * H2];
    int tid = threadIdx.x;
    int lane = tid & 31, wid = tid >> 5;
    int i = blockIdx.x * 8 + wid;

    {
        const float4* src = (const float4*)g_WgC;
        float4* dst = (float4*)scw;
#pragma unroll
        for (int q = 0; q < 4; q++) dst[tid + q * 256] = src[tid + q * 256];
    }

    int total = g_nbr_cnt[i];
    int cnt = min(total, CAP);
    const int* gl = g_nbr_idx + (size_t)i * CAP;
    for (int k = lane; k < cnt; k += 32) sidx[wid][k] = gl[k];
    __syncwarp();

    const float2* sup = (const float2*)g_support;
    float2 a0 = {0.f, 0.f}, a1 = {0.f, 0.f}, a2 = {0.f, 0.f}, a3 = {0.f, 0.f};
    float2 a4 = {0.f, 0.f}, a5 = {0.f, 0.f}, a6 = {0.f, 0.f}, a7 = {0.f, 0.f};
    int k = 0;
    for (; k + 8 <= cnt; k += 8) {
        int4 j0 = *(const int4*)&sidx[wid][k];
        int4 j1 = *(const int4*)&sidx[wid][k + 4];
        float2 p0 = sup[(size_t)j0.x * 32 + lane];
        float2 p1 = sup[(size_t)j0.y * 32 + lane];
        float2 p2 = sup[(size_t)j0.z * 32 + lane];
        float2 p3 = sup[(size_t)j0.w * 32 + lane];
        float2 p4 = sup[(size_t)j1.x * 32 + lane];
        float2 p5 = sup[(size_t)j1.y * 32 + lane];
        float2 p6 = sup[(size_t)j1.z * 32 + lane];
        float2 p7 = sup[(size_t)j1.w * 32 + lane];
        a0.x += p0.x; a0.y += p0.y;  a1.x += p1.x; a1.y += p1.y;
        a2.x += p2.x; a2.y += p2.y;  a3.x += p3.x; a3.y += p3.y;
        a4.x += p4.x; a4.y += p4.y;  a5.x += p5.x; a5.y += p5.y;
        a6.x += p6.x; a6.y += p6.y;  a7.x += p7.x; a7.y += p7.y;
    }
    for (; k + 4 <= cnt; k += 4) {
        int4 j0 = *(const int4*)&sidx[wid][k];
        float2 p0 = sup[(size_t)j0.x * 32 + lane];
        float2 p1 = sup[(size_t)j0.y * 32 + lane];
        float2 p2 = sup[(size_t)j0.z * 32 + lane];
        float2 p3 = sup[(size_t)j0.w * 32 + lane];
        a0.x += p0.x; a0.y += p0.y;  a1.x += p1.x; a1.y += p1.y;
        a2.x += p2.x; a2.y += p2.y;  a3.x += p3.x; a3.y += p3.y;
    }
    for (; k < cnt; k++) {
        float2 p = sup[(size_t)sidx[wid][k] * 32 + lane];
        a0.x += p.x; a0.y += p.y;
    }
    float dinv = 1.f / (float)total;
    float2 bg = ((const float2*)bg0)[lane];
    float2 h;
    h.x = leaky((a0.x + a1.x + a2.x + a3.x + a4.x + a5.x + a6.x + a7.x) * dinv + bg.x);
    h.y = leaky((a0.y + a1.y + a2.y + a3.y + a4.y + a5.y + a6.y + a7.y) * dinv + bg.y);
    *(float2*)&shp[wid][2 * lane] = h;
    __syncthreads();

    float s2 = 0.f, rr2 = 0.f;
#pragma unroll
    for (int kk = 0; kk < H1; kk += 4) {
        float4 hv = *(const float4*)&shp[wid][kk];
        float2 w0 = scw[(kk + 0) * H2 + lane];
        float2 w1 = scw[(kk + 1) * H2 + lane];
        float2 w2 = scw[(kk + 2) * H2 + lane];
        float2 w3 = scw[(kk + 3) * H2 + lane];
        s2  = fmaf(hv.x, w0.x, s2);  rr2 = fmaf(hv.x, w0.y, rr2);
        s2  = fmaf(hv.y, w1.x, s2);  rr2 = fmaf(hv.y, w1.y, rr2);
        s2  = fmaf(hv.z, w2.x, s2);  rr2 = fmaf(hv.z, w2.y, rr2);
        s2  = fmaf(hv.w, w3.x, s2);  rr2 = fmaf(hv.w, w3.y, rr2);
    }
    g_support2[(size_t)i * H2 + lane] = s2;
    g_resid[(size_t)i * H2 + lane]    = rr2 + br[lane];
}

// ================= kernel 4: gnn layer 2 + residual -> out (MLP=16) =======
__global__ void __launch_bounds__(256)
gnn2_kernel(const float* __restrict__ bg1,
            float* __restrict__ out) {
    __shared__ int sidx[8][CAP];
    int tid = threadIdx.x;
    int lane = tid & 31, wid = tid >> 5;
    int i = blockIdx.x * 8 + wid;
    int total = g_nbr_cnt[i];
    int cnt = min(total, CAP);
    const int* gl = g_nbr_idx + (size_t)i * CAP;
    for (int k = lane; k < cnt; k += 32) sidx[wid][k] = gl[k];
    __syncwarp();

    const float* sup2 = g_support2;
    float a0 = 0.f, a1 = 0.f, a2 = 0.f, a3 = 0.f;
    float a4 = 0.f, a5 = 0.f, a6 = 0.f, a7 = 0.f;
    float b0 = 0.f, b1 = 0.f, b2 = 0.f, b3 = 0.f;
    float b4 = 0.f, b5 = 0.f, b6 = 0.f, b7 = 0.f;
    int k = 0;
    for (; k + 16 <= cnt; k += 16) {
        int4 j0 = *(const int4*)&sidx[wid][k];
        int4 j1 = *(const int4*)&sidx[wid][k + 4];
        int4 j2 = *(const int4*)&sidx[wid][k + 8];
        int4 j3 = *(const int4*)&sidx[wid][k + 12];
        a0 += sup2[(size_t)j0.x * H2 + lane];
        a1 += sup2[(size_t)j0.y * H2 + lane];
        a2 += sup2[(size_t)j0.z * H2 + lane];
        a3 += sup2[(size_t)j0.w * H2 + lane];
        a4 += sup2[(size_t)j1.x * H2 + lane];
        a5 += sup2[(size_t)j1.y * H2 + lane];
        a6 += sup2[(size_t)j1.z * H2 + lane];
        a7 += sup2[(size_t)j1.w * H2 + lane];
        b0 += sup2[(size_t)j2.x * H2 + lane];
        b1 += sup2[(size_t)j2.y * H2 + lane];
        b2 += sup2[(size_t)j2.z * H2 + lane];
        b3 += sup2[(size_t)j2.w * H2 + lane];
        b4 += sup2[(size_t)j3.x * H2 + lane];
        b5 += sup2[(size_t)j3.y * H2 + lane];
        b6 += sup2[(size_t)j3.z * H2 + lane];
        b7 += sup2[(size_t)j3.w * H2 + lane];
    }
    for (; k + 4 <= cnt; k += 4) {
        int4 j0 = *(const int4*)&sidx[wid][k];
        a0 += sup2[(size_t)j0.x * H2 + lane];
        a1 += sup2[(size_t)j0.y * H2 + lane];
        a2 += sup2[(size_t)j0.z * H2 + lane];
        a3 += sup2[(size_t)j0.w * H2 + lane];
    }
    for (; k < cnt; k++) a0 += sup2[(size_t)sidx[wid][k] * H2 + lane];

    float agg = (a0 + a1 + a2 + a3 + a4 + a5 + a6 + a7)
              + (b0 + b1 + b2 + b3 + b4 + b5 + b6 + b7);
    float v = leaky(agg * (1.f / (float)total) + bg1[lane]);
    out[(size_t)i * H2 + lane] = v + g_resid[(size_t)i * H2 + lane];
}

extern "C" void kernel_launch(void* const* d_in, const int* in_sizes, int n_in,
                              void* d_out, int out_size) {
    const float* x   = (const float*)d_in[0];
    const float* adj = (const float*)d_in[1];
    const float* W1  = (const float*)d_in[2];
    const float* a1  = (const float*)d_in[3];
    const float* W2  = (const float*)d_in[4];
    const float* a2  = (const float*)d_in[5];
    const float* W3  = (const float*)d_in[6];
    const float* a3  = (const float*)d_in[7];
    const float* Wg0 = (const float*)d_in[8];
    const float* bg0 = (const float*)d_in[9];
    const float* Wg1 = (const float*)d_in[10];
    const float* bg1 = (const float*)d_in[11];
    const float* Wr  = (const float*)d_in[12];
    const float* br  = (const float*)d_in[13];
    const void*  rel = d_in[14];
    float* out = (float*)d_out;

    wh_kernel<<<dim3(64, 3), 256>>>(x, W1, a1, W2, a2, W3, a3, Wg1, Wr);
    scan_attn_fuse_kernel<<<N, 256>>>(adj, rel, Wg0);
    gnn1_kernel<<<N / 8, 256>>>(bg0, br);
    gnn2_kernel<<<N / 8, 256>>>(bg1, out);
}